// round 3
// baseline (speedup 1.0000x reference)
#include <cuda_runtime.h>
#include <stdint.h>

// Problem constants
#define N_TOK 65536
#define D     256
#define K     1024

// GEMM tiling
#define BM 128
#define BN 128
#define BK 16
#define TM 8
#define TN 8

// Scratch (no cudaMalloc allowed)
__device__ float g_counts[K];
__device__ float g_dw[K * D];
__device__ float g_cs[K];
__device__ unsigned long long g_loss;

// ---------------------------------------------------------------------------
// Zero scratch
// ---------------------------------------------------------------------------
__global__ void vq_prep() {
    int i = blockIdx.x * blockDim.x + threadIdx.x;
    if (i < K * D) g_dw[i] = 0.0f;
    if (i < K)     g_counts[i] = 0.0f;
    if (i == 0)    g_loss = 0ull;
}

// ---------------------------------------------------------------------------
// Codebook squared norms: g_cs[k] = sum_d CB[k,d]^2   (one warp per row)
// ---------------------------------------------------------------------------
__global__ void vq_cs(const float* __restrict__ CB) {
    int w = (blockIdx.x * blockDim.x + threadIdx.x) >> 5;
    int lane = threadIdx.x & 31;
    if (w >= K) return;
    const float* row = CB + (size_t)w * D + lane * 8;
    float4 v0 = *(const float4*)row;
    float4 v1 = *(const float4*)(row + 4);
    float s = v0.x * v0.x + v0.y * v0.y + v0.z * v0.z + v0.w * v0.w
            + v1.x * v1.x + v1.y * v1.y + v1.z * v1.z + v1.w * v1.w;
    #pragma unroll
    for (int o = 16; o > 0; o >>= 1) s += __shfl_xor_sync(0xffffffffu, s, o);
    if (lane == 0) g_cs[w] = s;
}

// ---------------------------------------------------------------------------
// Main fused kernel: distance GEMM + argmin + gather + scatter + loss
// One block handles BM=128 tokens against all K=1024 codes.
// ---------------------------------------------------------------------------
__global__ __launch_bounds__(256, 2) void vq_main(
    const float* __restrict__ X, const float* __restrict__ CB,
    float* __restrict__ outQ, float* __restrict__ outIdx)
{
    __shared__ float As[BK][BM];
    __shared__ float Bs[BK][BN];
    __shared__ float rxs[BM];
    __shared__ float red_d[16][BM];
    __shared__ int   red_i[16][BM];
    __shared__ int   bestI[BM];
    __shared__ float bestD[BM];

    const int tid = threadIdx.x;
    const int tx = tid & 15;   // code-column group
    const int ty = tid >> 4;   // token-row group
    const int tok0 = blockIdx.x * BM;

    // Per-token ||x||^2 (constant offset; reproduces reference fp32 grid)
    if (tid < BM) {
        const float* xr = X + (size_t)(tok0 + tid) * D;
        float s = 0.0f;
        #pragma unroll 8
        for (int j = 0; j < D; j += 4) {
            float4 v = *(const float4*)(xr + j);
            s += v.x * v.x; s += v.y * v.y; s += v.z * v.z; s += v.w * v.w;
        }
        rxs[tid] = s;
    }

    float bd[TM];
    int   bi[TM];
    #pragma unroll
    for (int r = 0; r < TM; r++) { bd[r] = 3.4e38f; bi[r] = 0; }

    __syncthreads();

    for (int kc = 0; kc < K / BN; kc++) {
        float acc[TM][TN];
        #pragma unroll
        for (int r = 0; r < TM; r++)
            #pragma unroll
            for (int c = 0; c < TN; c++) acc[r][c] = 0.0f;

        for (int dd = 0; dd < D; dd += BK) {
            // Stage A (tokens) and B (codes) tiles, transposed into [k][row]
            #pragma unroll
            for (int i = 0; i < 2; i++) {
                int li = tid + i * 256;           // 0..511
                int r  = li >> 2;                 // 0..127
                int cg = (li & 3) << 2;           // 0,4,8,12
                float4 va = *(const float4*)(X  + (size_t)(tok0 + r) * D + dd + cg);
                As[cg + 0][r] = va.x; As[cg + 1][r] = va.y;
                As[cg + 2][r] = va.z; As[cg + 3][r] = va.w;
                float4 vb = *(const float4*)(CB + (size_t)(kc * BN + r) * D + dd + cg);
                Bs[cg + 0][r] = vb.x; Bs[cg + 1][r] = vb.y;
                Bs[cg + 2][r] = vb.z; Bs[cg + 3][r] = vb.w;
            }
            __syncthreads();

            #pragma unroll
            for (int k = 0; k < BK; k++) {
                float a[TM], b[TN];
                *(float4*)(a)     = *(const float4*)&As[k][ty * TM];
                *(float4*)(a + 4) = *(const float4*)&As[k][ty * TM + 4];
                *(float4*)(b)     = *(const float4*)&Bs[k][tx * TN];
                *(float4*)(b + 4) = *(const float4*)&Bs[k][tx * TN + 4];
                #pragma unroll
                for (int r = 0; r < TM; r++)
                    #pragma unroll
                    for (int c = 0; c < TN; c++)
                        acc[r][c] = fmaf(a[r], b[c], acc[r][c]);
            }
            __syncthreads();
        }

        // Chunk epilogue: d = (rx + cs) - 2*dot ; running argmin (strict <,
        // k ascending -> first-index tie-break within this thread)
        #pragma unroll
        for (int c = 0; c < TN; c++) {
            int kidx = kc * BN + tx * TN + c;
            float csv = g_cs[kidx];
            #pragma unroll
            for (int r = 0; r < TM; r++) {
                float t = rxs[ty * TM + r] + csv;
                float d = t - 2.0f * acc[r][c];
                if (d < bd[r]) { bd[r] = d; bi[r] = kidx; }
            }
        }
    }

    // Cross-thread argmin reduce (16 tx threads share each token row)
    #pragma unroll
    for (int r = 0; r < TM; r++) {
        red_d[tx][ty * TM + r] = bd[r];
        red_i[tx][ty * TM + r] = bi[r];
    }
    __syncthreads();

    if (tid < BM) {
        float best = 3.4e38f;
        int bidx = K;
        #pragma unroll
        for (int t = 0; t < 16; t++) {
            float d = red_d[t][tid];
            int   ii = red_i[t][tid];
            if (d < best || (d == best && ii < bidx)) { best = d; bidx = ii; }
        }
        bestI[tid] = bidx;
        bestD[tid] = best;
        outIdx[tok0 + tid] = (float)bidx;
        atomicAdd(&g_counts[bidx], 1.0f);   // exact: integer-valued fp32 sums
    }
    __syncthreads();

    // Deterministic loss accumulation: scaled int64
    if (tid == 0) {
        double s = 0.0;
        for (int r = 0; r < BM; r++) s += (double)bestD[r];
        atomicAdd(&g_loss, (unsigned long long)llrint(s * 1048576.0));
    }

    // Gather quantized rows + scatter dw
    for (int i = tid; i < BM * (D / 4); i += 256) {
        int row = i >> 6;
        int c4  = (i & 63) << 2;
        int b   = bestI[row];
        float4 q = *(const float4*)(CB + (size_t)b * D + c4);
        *(float4*)(outQ + (size_t)(tok0 + row) * D + c4) = q;
        float4 xv = *(const float4*)(X + (size_t)(tok0 + row) * D + c4);
        float* dwp = g_dw + (size_t)b * D + c4;
        atomicAdd(dwp + 0, xv.x);
        atomicAdd(dwp + 1, xv.y);
        atomicAdd(dwp + 2, xv.z);
        atomicAdd(dwp + 3, xv.w);
    }
}

// ---------------------------------------------------------------------------
// Finalize: new_cs (Laplace-smoothed), perplexity, vq_loss. One block, K thr.
// ---------------------------------------------------------------------------
__global__ void vq_finalize(const float* __restrict__ ecs,
                            float* __restrict__ out_cs,
                            float* __restrict__ out_perp,
                            float* __restrict__ out_loss)
{
    __shared__ float sbuf[K];
    int k = threadIdx.x;
    float cnt = g_counts[k];
    float cn = 0.99f * ecs[k] + 0.01f * cnt;

    sbuf[k] = cn;
    __syncthreads();
    for (int s = K / 2; s > 0; s >>= 1) {
        if (k < s) sbuf[k] += sbuf[k + s];
        __syncthreads();
    }
    float ntot = sbuf[0];
    __syncthreads();

    out_cs[k] = (cn + 1e-5f) / (ntot + 0.01024f) * ntot;

    float p = cnt * (1.0f / 65536.0f);
    sbuf[k] = p * logf(p + 1e-10f);
    __syncthreads();
    for (int s = K / 2; s > 0; s >>= 1) {
        if (k < s) sbuf[k] += sbuf[k + s];
        __syncthreads();
    }
    if (k == 0) {
        out_perp[0] = expf(-sbuf[0]);
        double loss = (double)g_loss * (1.0 / 1048576.0) / (65536.0 * 256.0);
        out_loss[0] = 0.25f * (float)loss;
    }
}

// ---------------------------------------------------------------------------
// EMA codebook update + normalized weight
// ---------------------------------------------------------------------------
__global__ void vq_ema(const float* __restrict__ emaw,
                       const float* __restrict__ ncs,
                       float* __restrict__ outE,
                       float* __restrict__ outW)
{
    int i = blockIdx.x * blockDim.x + threadIdx.x;   // < K*D
    float w = 0.99f * emaw[i] + 0.01f * g_dw[i];
    outE[i] = w;
    outW[i] = w / ncs[i >> 8];
}

// ---------------------------------------------------------------------------
// Launch: outputs concatenated in reference return order, all float32:
//   quantized_st [N*D] | vq_loss [1] | indices [N] | perplexity [1]
//   | new_cs [K] | new_ema_w [K*D] | new_weight [K*D]
// ---------------------------------------------------------------------------
extern "C" void kernel_launch(void* const* d_in, const int* in_sizes, int n_in,
                              void* d_out, int out_size)
{
    const float* X   = (const float*)d_in[0];   // inputs  [N, D]
    const float* CB  = (const float*)d_in[1];   // codebook [K, D]
    const float* ECS = (const float*)d_in[2];   // ema_cluster_size [K]
    const float* EW  = (const float*)d_in[3];   // ema_w [K, D]
    float* out = (float*)d_out;

    const size_t OQ = 0;
    const size_t OL = (size_t)N_TOK * D;        // vq_loss
    const size_t OI = OL + 1;                   // indices
    const size_t OP = OI + N_TOK;               // perplexity
    const size_t OC = OP + 1;                   // new_cs
    const size_t OE = OC + K;                   // new_ema_w
    const size_t OW = OE + (size_t)K * D;       // new_weight

    vq_prep<<<(K * D + 255) / 256, 256>>>();
    vq_cs<<<K / 8, 256>>>(CB);
    vq_main<<<N_TOK / BM, 256>>>(X, CB, out + OQ, out + OI);
    vq_finalize<<<1, K>>>(ECS, out + OC, out + OP, out + OL);
    vq_ema<<<(K * D) / 256, 256>>>(EW, out + OC, out + OE, out + OW);
}

// round 4
// speedup vs baseline: 1.0584x; 1.0584x over previous
#include <cuda_runtime.h>
#include <stdint.h>

// Problem constants
#define N_TOK 65536
#define D     256
#define K     1024

// GEMM tiling
#define BM 128
#define BN 128
#define BK 16
#define TM 8
#define TN 8

// Scratch (no cudaMalloc allowed)
__device__ float g_counts[K];
__device__ float g_dw[K * D];
__device__ float g_cs[K];
__device__ unsigned long long g_loss;

// ---------------------------------------------------------------------------
// Zero scratch
// ---------------------------------------------------------------------------
__global__ void vq_prep() {
    int i = blockIdx.x * blockDim.x + threadIdx.x;
    if (i < K * D) g_dw[i] = 0.0f;
    if (i < K)     g_counts[i] = 0.0f;
    if (i == 0)    g_loss = 0ull;
}

// ---------------------------------------------------------------------------
// Codebook squared norms: g_cs[k] = sum_d CB[k,d]^2   (one warp per row)
// ---------------------------------------------------------------------------
__global__ void vq_cs(const float* __restrict__ CB) {
    int w = (blockIdx.x * blockDim.x + threadIdx.x) >> 5;
    int lane = threadIdx.x & 31;
    if (w >= K) return;
    const float* row = CB + (size_t)w * D + lane * 8;
    float4 v0 = *(const float4*)row;
    float4 v1 = *(const float4*)(row + 4);
    float s = v0.x * v0.x + v0.y * v0.y + v0.z * v0.z + v0.w * v0.w
            + v1.x * v1.x + v1.y * v1.y + v1.z * v1.z + v1.w * v1.w;
    #pragma unroll
    for (int o = 16; o > 0; o >>= 1) s += __shfl_xor_sync(0xffffffffu, s, o);
    if (lane == 0) g_cs[w] = s;
}

// ---------------------------------------------------------------------------
// Main fused kernel: distance GEMM + argmin + gather + scatter + loss
// One block handles BM=128 tokens against all K=1024 codes.
// ---------------------------------------------------------------------------
__global__ __launch_bounds__(256, 2) void vq_main(
    const float* __restrict__ X, const float* __restrict__ CB,
    float* __restrict__ outQ, float* __restrict__ outIdx)
{
    __shared__ float As[BK][BM];
    __shared__ float Bs[BK][BN];
    __shared__ float rxs[BM];
    __shared__ float red_d[16][BM];
    __shared__ int   red_i[16][BM];
    __shared__ int   bestI[BM];
    __shared__ float bestD[BM];

    const int tid = threadIdx.x;
    const int tx = tid & 15;   // code-column group
    const int ty = tid >> 4;   // token-row group
    const int tok0 = blockIdx.x * BM;

    // Per-token ||x||^2 (constant offset; reproduces reference fp32 grid)
    if (tid < BM) {
        const float* xr = X + (size_t)(tok0 + tid) * D;
        float s = 0.0f;
        #pragma unroll 8
        for (int j = 0; j < D; j += 4) {
            float4 v = *(const float4*)(xr + j);
            s += v.x * v.x; s += v.y * v.y; s += v.z * v.z; s += v.w * v.w;
        }
        rxs[tid] = s;
    }

    float bd[TM];
    int   bi[TM];
    #pragma unroll
    for (int r = 0; r < TM; r++) { bd[r] = 3.4e38f; bi[r] = 0; }

    __syncthreads();

    for (int kc = 0; kc < K / BN; kc++) {
        float acc[TM][TN];
        #pragma unroll
        for (int r = 0; r < TM; r++)
            #pragma unroll
            for (int c = 0; c < TN; c++) acc[r][c] = 0.0f;

        for (int dd = 0; dd < D; dd += BK) {
            // Stage A (tokens) and B (codes) tiles, transposed into [k][row]
            #pragma unroll
            for (int i = 0; i < 2; i++) {
                int li = tid + i * 256;           // 0..511
                int r  = li >> 2;                 // 0..127
                int cg = (li & 3) << 2;           // 0,4,8,12
                float4 va = *(const float4*)(X  + (size_t)(tok0 + r) * D + dd + cg);
                As[cg + 0][r] = va.x; As[cg + 1][r] = va.y;
                As[cg + 2][r] = va.z; As[cg + 3][r] = va.w;
                float4 vb = *(const float4*)(CB + (size_t)(kc * BN + r) * D + dd + cg);
                Bs[cg + 0][r] = vb.x; Bs[cg + 1][r] = vb.y;
                Bs[cg + 2][r] = vb.z; Bs[cg + 3][r] = vb.w;
            }
            __syncthreads();

            #pragma unroll
            for (int k = 0; k < BK; k++) {
                float a[TM], b[TN];
                *(float4*)(a)     = *(const float4*)&As[k][ty * TM];
                *(float4*)(a + 4) = *(const float4*)&As[k][ty * TM + 4];
                *(float4*)(b)     = *(const float4*)&Bs[k][tx * TN];
                *(float4*)(b + 4) = *(const float4*)&Bs[k][tx * TN + 4];
                #pragma unroll
                for (int r = 0; r < TM; r++)
                    #pragma unroll
                    for (int c = 0; c < TN; c++)
                        acc[r][c] = fmaf(a[r], b[c], acc[r][c]);
            }
            __syncthreads();
        }

        // Chunk epilogue: d = (rx + cs) - 2*dot ; running argmin (strict <,
        // k ascending -> first-index tie-break within this thread)
        #pragma unroll
        for (int c = 0; c < TN; c++) {
            int kidx = kc * BN + tx * TN + c;
            float csv = g_cs[kidx];
            #pragma unroll
            for (int r = 0; r < TM; r++) {
                float t = rxs[ty * TM + r] + csv;
                float d = t - 2.0f * acc[r][c];
                if (d < bd[r]) { bd[r] = d; bi[r] = kidx; }
            }
        }
    }

    // Cross-thread argmin reduce (16 tx threads share each token row)
    #pragma unroll
    for (int r = 0; r < TM; r++) {
        red_d[tx][ty * TM + r] = bd[r];
        red_i[tx][ty * TM + r] = bi[r];
    }
    __syncthreads();

    if (tid < BM) {
        float best = 3.4e38f;
        int bidx = K;
        #pragma unroll
        for (int t = 0; t < 16; t++) {
            float d = red_d[t][tid];
            int   ii = red_i[t][tid];
            if (d < best || (d == best && ii < bidx)) { best = d; bidx = ii; }
        }
        bestI[tid] = bidx;
        bestD[tid] = best;
        outIdx[tok0 + tid] = (float)bidx;
        atomicAdd(&g_counts[bidx], 1.0f);   // exact: integer-valued fp32 sums
    }
    __syncthreads();

    // Deterministic loss accumulation: scaled int64
    if (tid == 0) {
        double s = 0.0;
        for (int r = 0; r < BM; r++) s += (double)bestD[r];
        atomicAdd(&g_loss, (unsigned long long)llrint(s * 1048576.0));
    }

    // Gather quantized rows + scatter dw
    for (int i = tid; i < BM * (D / 4); i += 256) {
        int row = i >> 6;
        int c4  = (i & 63) << 2;
        int b   = bestI[row];
        float4 q = *(const float4*)(CB + (size_t)b * D + c4);
        *(float4*)(outQ + (size_t)(tok0 + row) * D + c4) = q;
        float4 xv = *(const float4*)(X + (size_t)(tok0 + row) * D + c4);
        float* dwp = g_dw + (size_t)b * D + c4;
        atomicAdd(dwp + 0, xv.x);
        atomicAdd(dwp + 1, xv.y);
        atomicAdd(dwp + 2, xv.z);
        atomicAdd(dwp + 3, xv.w);
    }
}

// ---------------------------------------------------------------------------
// Finalize: new_cs (Laplace-smoothed), perplexity, vq_loss. One block, K thr.
// ---------------------------------------------------------------------------
__global__ void vq_finalize(const float* __restrict__ ecs,
                            float* __restrict__ out_cs,
                            float* __restrict__ out_perp,
                            float* __restrict__ out_loss)
{
    __shared__ float sbuf[K];
    int k = threadIdx.x;
    float cnt = g_counts[k];
    float cn = 0.99f * ecs[k] + 0.01f * cnt;

    sbuf[k] = cn;
    __syncthreads();
    for (int s = K / 2; s > 0; s >>= 1) {
        if (k < s) sbuf[k] += sbuf[k + s];
        __syncthreads();
    }
    float ntot = sbuf[0];
    __syncthreads();

    out_cs[k] = (cn + 1e-5f) / (ntot + 0.01024f) * ntot;

    float p = cnt * (1.0f / 65536.0f);
    sbuf[k] = p * logf(p + 1e-10f);
    __syncthreads();
    for (int s = K / 2; s > 0; s >>= 1) {
        if (k < s) sbuf[k] += sbuf[k + s];
        __syncthreads();
    }
    if (k == 0) {
        out_perp[0] = expf(-sbuf[0]);
        double loss = (double)g_loss * (1.0 / 1048576.0) / (65536.0 * 256.0);
        out_loss[0] = 0.25f * (float)loss;
    }
}

// ---------------------------------------------------------------------------
// EMA codebook update + normalized weight
// ---------------------------------------------------------------------------
__global__ void vq_ema(const float* __restrict__ emaw,
                       const float* __restrict__ ncs,
                       float* __restrict__ outE,
                       float* __restrict__ outW)
{
    int i = blockIdx.x * blockDim.x + threadIdx.x;   // < K*D
    float w = 0.99f * emaw[i] + 0.01f * g_dw[i];
    outE[i] = w;
    outW[i] = w / ncs[i >> 8];
}

// ---------------------------------------------------------------------------
// Launch: outputs concatenated in reference return order, all float32:
//   quantized_st [N*D] | vq_loss [1] | indices [N] | perplexity [1]
//   | new_cs [K] | new_ema_w [K*D] | new_weight [K*D]
// ---------------------------------------------------------------------------
extern "C" void kernel_launch(void* const* d_in, const int* in_sizes, int n_in,
                              void* d_out, int out_size)
{
    const float* X   = (const float*)d_in[0];   // inputs  [N, D]
    const float* CB  = (const float*)d_in[1];   // codebook [K, D]
    const float* ECS = (const float*)d_in[2];   // ema_cluster_size [K]
    const float* EW  = (const float*)d_in[3];   // ema_w [K, D]
    float* out = (float*)d_out;

    const size_t OQ = 0;
    const size_t OL = (size_t)N_TOK * D;        // vq_loss
    const size_t OI = OL + 1;                   // indices
    const size_t OP = OI + N_TOK;               // perplexity
    const size_t OC = OP + 1;                   // new_cs
    const size_t OE = OC + K;                   // new_ema_w
    const size_t OW = OE + (size_t)K * D;       // new_weight

    vq_prep<<<(K * D + 255) / 256, 256>>>();
    vq_cs<<<K / 8, 256>>>(CB);
    vq_main<<<N_TOK / BM, 256>>>(X, CB, out + OQ, out + OI);
    vq_finalize<<<1, K>>>(ECS, out + OC, out + OP, out + OL);
    vq_ema<<<(K * D) / 256, 256>>>(EW, out + OC, out + OE, out + OW);
}

// round 5
// speedup vs baseline: 1.0859x; 1.0260x over previous
#include <cuda_runtime.h>
#include <stdint.h>

// Problem constants
#define N_TOK 65536
#define D     256
#define K     1024

// GEMM tiling
#define BM 128
#define BN 128
#define BK 16
#define TM 8
#define TN 8

// Packed fp32x2 FMA (SASS FFMA2, sm_103a). Exact per-lane fp32 FMA.
#define FMA_F32X2(d, a, b, c) \
    asm("fma.rn.f32x2 %0, %1, %2, %3;" : "=l"(d) : "l"(a), "l"(b), "l"(c))
#define PACK_DUP_F32X2(out, f) \
    asm("mov.b64 %0, {%1, %1};" : "=l"(out) : "r"(__float_as_uint(f)))
#define UNPACK_F32X2(lo, hi, in) \
    asm("mov.b64 {%0, %1}, %2;" : "=f"(lo), "=f"(hi) : "l"(in))

// Scratch (no cudaMalloc allowed)
__device__ float g_counts[K];
__device__ float g_dw[K * D];
__device__ float g_cs[K];
__device__ unsigned long long g_loss;

// ---------------------------------------------------------------------------
// Zero scratch
// ---------------------------------------------------------------------------
__global__ void vq_prep() {
    int i = blockIdx.x * blockDim.x + threadIdx.x;
    if (i < K * D) g_dw[i] = 0.0f;
    if (i < K)     g_counts[i] = 0.0f;
    if (i == 0)    g_loss = 0ull;
}

// ---------------------------------------------------------------------------
// Codebook squared norms: g_cs[k] = sum_d CB[k,d]^2   (one warp per row)
// ---------------------------------------------------------------------------
__global__ void vq_cs(const float* __restrict__ CB) {
    int w = (blockIdx.x * blockDim.x + threadIdx.x) >> 5;
    int lane = threadIdx.x & 31;
    if (w >= K) return;
    const float* row = CB + (size_t)w * D + lane * 8;
    float4 v0 = *(const float4*)row;
    float4 v1 = *(const float4*)(row + 4);
    float s = v0.x * v0.x + v0.y * v0.y + v0.z * v0.z + v0.w * v0.w
            + v1.x * v1.x + v1.y * v1.y + v1.z * v1.z + v1.w * v1.w;
    #pragma unroll
    for (int o = 16; o > 0; o >>= 1) s += __shfl_xor_sync(0xffffffffu, s, o);
    if (lane == 0) g_cs[w] = s;
}

// ---------------------------------------------------------------------------
// Main fused kernel: distance GEMM (FFMA2) + argmin + gather + scatter + loss
// One block handles BM=128 tokens against all K=1024 codes.
// ---------------------------------------------------------------------------
__global__ __launch_bounds__(256, 2) void vq_main(
    const float* __restrict__ X, const float* __restrict__ CB,
    float* __restrict__ outQ, float* __restrict__ outIdx)
{
    __shared__ __align__(16) float As[BK][BM];
    __shared__ __align__(16) float Bs[BK][BN];
    __shared__ float rxs[BM];
    __shared__ float red_d[16][BM];
    __shared__ int   red_i[16][BM];
    __shared__ int   bestI[BM];
    __shared__ float bestD[BM];

    const int tid = threadIdx.x;
    const int tx = tid & 15;   // code-column group
    const int ty = tid >> 4;   // token-row group
    const int tok0 = blockIdx.x * BM;

    // Per-token ||x||^2 (constant offset; reproduces reference fp32 grid)
    if (tid < BM) {
        const float* xr = X + (size_t)(tok0 + tid) * D;
        float s = 0.0f;
        #pragma unroll 8
        for (int j = 0; j < D; j += 4) {
            float4 v = *(const float4*)(xr + j);
            s += v.x * v.x; s += v.y * v.y; s += v.z * v.z; s += v.w * v.w;
        }
        rxs[tid] = s;
    }

    float bd[TM];
    int   bi[TM];
    #pragma unroll
    for (int r = 0; r < TM; r++) { bd[r] = 3.4e38f; bi[r] = 0; }

    __syncthreads();

    for (int kc = 0; kc < K / BN; kc++) {
        // acc2[r][c2] packs columns (2*c2, 2*c2+1) of the 8x8 micro-tile
        unsigned long long acc2[TM][TN / 2];
        #pragma unroll
        for (int r = 0; r < TM; r++)
            #pragma unroll
            for (int c = 0; c < TN / 2; c++) acc2[r][c] = 0ull;

        for (int dd = 0; dd < D; dd += BK) {
            // Stage A (tokens) and B (codes) tiles, transposed into [k][row]
            #pragma unroll
            for (int i = 0; i < 2; i++) {
                int li = tid + i * 256;           // 0..511
                int r  = li >> 2;                 // 0..127
                int cg = (li & 3) << 2;           // 0,4,8,12
                float4 va = *(const float4*)(X  + (size_t)(tok0 + r) * D + dd + cg);
                As[cg + 0][r] = va.x; As[cg + 1][r] = va.y;
                As[cg + 2][r] = va.z; As[cg + 3][r] = va.w;
                float4 vb = *(const float4*)(CB + (size_t)(kc * BN + r) * D + dd + cg);
                Bs[cg + 0][r] = vb.x; Bs[cg + 1][r] = vb.y;
                Bs[cg + 2][r] = vb.z; Bs[cg + 3][r] = vb.w;
            }
            __syncthreads();

            #pragma unroll
            for (int k = 0; k < BK; k++) {
                float a_[TM];
                *(float4*)(a_)     = *(const float4*)&As[k][ty * TM];
                *(float4*)(a_ + 4) = *(const float4*)&As[k][ty * TM + 4];
                // b pairs come directly as u64 views of the float4 loads
                ulonglong2 b01 = *(const ulonglong2*)&Bs[k][tx * TN];
                ulonglong2 b23 = *(const ulonglong2*)&Bs[k][tx * TN + 4];
                #pragma unroll
                for (int r = 0; r < TM; r++) {
                    unsigned long long pa;
                    PACK_DUP_F32X2(pa, a_[r]);
                    FMA_F32X2(acc2[r][0], pa, b01.x, acc2[r][0]);
                    FMA_F32X2(acc2[r][1], pa, b01.y, acc2[r][1]);
                    FMA_F32X2(acc2[r][2], pa, b23.x, acc2[r][2]);
                    FMA_F32X2(acc2[r][3], pa, b23.y, acc2[r][3]);
                }
            }
            __syncthreads();
        }

        // Chunk epilogue: d = (rx + cs) - 2*dot ; running argmin (strict <,
        // k ascending -> first-index tie-break within this thread)
        #pragma unroll
        for (int c2 = 0; c2 < TN / 2; c2++) {
            int kidx = kc * BN + tx * TN + 2 * c2;
            float cs0 = g_cs[kidx];
            float cs1 = g_cs[kidx + 1];
            #pragma unroll
            for (int r = 0; r < TM; r++) {
                float lo, hi;
                UNPACK_F32X2(lo, hi, acc2[r][c2]);
                float rx = rxs[ty * TM + r];
                float d0 = (rx + cs0) - 2.0f * lo;
                float d1 = (rx + cs1) - 2.0f * hi;
                if (d0 < bd[r]) { bd[r] = d0; bi[r] = kidx; }
                if (d1 < bd[r]) { bd[r] = d1; bi[r] = kidx + 1; }
            }
        }
    }

    // Cross-thread argmin reduce (16 tx threads share each token row)
    #pragma unroll
    for (int r = 0; r < TM; r++) {
        red_d[tx][ty * TM + r] = bd[r];
        red_i[tx][ty * TM + r] = bi[r];
    }
    __syncthreads();

    if (tid < BM) {
        float best = 3.4e38f;
        int bidx = K;
        #pragma unroll
        for (int t = 0; t < 16; t++) {
            float d = red_d[t][tid];
            int   ii = red_i[t][tid];
            if (d < best || (d == best && ii < bidx)) { best = d; bidx = ii; }
        }
        bestI[tid] = bidx;
        bestD[tid] = best;
        outIdx[tok0 + tid] = (float)bidx;
        atomicAdd(&g_counts[bidx], 1.0f);   // exact: integer-valued fp32 sums
    }
    __syncthreads();

    // Deterministic loss accumulation: scaled int64
    if (tid == 0) {
        double s = 0.0;
        for (int r = 0; r < BM; r++) s += (double)bestD[r];
        atomicAdd(&g_loss, (unsigned long long)llrint(s * 1048576.0));
    }

    // Gather quantized rows + scatter dw
    for (int i = tid; i < BM * (D / 4); i += 256) {
        int row = i >> 6;
        int c4  = (i & 63) << 2;
        int b   = bestI[row];
        float4 q = *(const float4*)(CB + (size_t)b * D + c4);
        *(float4*)(outQ + (size_t)(tok0 + row) * D + c4) = q;
        float4 xv = *(const float4*)(X + (size_t)(tok0 + row) * D + c4);
        float* dwp = g_dw + (size_t)b * D + c4;
        atomicAdd(dwp + 0, xv.x);
        atomicAdd(dwp + 1, xv.y);
        atomicAdd(dwp + 2, xv.z);
        atomicAdd(dwp + 3, xv.w);
    }
}

// ---------------------------------------------------------------------------
// Finalize: new_cs (Laplace-smoothed), perplexity, vq_loss. One block, K thr.
// ---------------------------------------------------------------------------
__global__ void vq_finalize(const float* __restrict__ ecs,
                            float* __restrict__ out_cs,
                            float* __restrict__ out_perp,
                            float* __restrict__ out_loss)
{
    __shared__ float sbuf[K];
    int k = threadIdx.x;
    float cnt = g_counts[k];
    float cn = 0.99f * ecs[k] + 0.01f * cnt;

    sbuf[k] = cn;
    __syncthreads();
    for (int s = K / 2; s > 0; s >>= 1) {
        if (k < s) sbuf[k] += sbuf[k + s];
        __syncthreads();
    }
    float ntot = sbuf[0];
    __syncthreads();

    out_cs[k] = (cn + 1e-5f) / (ntot + 0.01024f) * ntot;

    float p = cnt * (1.0f / 65536.0f);
    sbuf[k] = p * logf(p + 1e-10f);
    __syncthreads();
    for (int s = K / 2; s > 0; s >>= 1) {
        if (k < s) sbuf[k] += sbuf[k + s];
        __syncthreads();
    }
    if (k == 0) {
        out_perp[0] = expf(-sbuf[0]);
        double loss = (double)g_loss * (1.0 / 1048576.0) / (65536.0 * 256.0);
        out_loss[0] = 0.25f * (float)loss;
    }
}

// ---------------------------------------------------------------------------
// EMA codebook update + normalized weight
// ---------------------------------------------------------------------------
__global__ void vq_ema(const float* __restrict__ emaw,
                       const float* __restrict__ ncs,
                       float* __restrict__ outE,
                       float* __restrict__ outW)
{
    int i = blockIdx.x * blockDim.x + threadIdx.x;   // < K*D
    float w = 0.99f * emaw[i] + 0.01f * g_dw[i];
    outE[i] = w;
    outW[i] = w / ncs[i >> 8];
}

// ---------------------------------------------------------------------------
// Launch: outputs concatenated in reference return order, all float32:
//   quantized_st [N*D] | vq_loss [1] | indices [N] | perplexity [1]
//   | new_cs [K] | new_ema_w [K*D] | new_weight [K*D]
// ---------------------------------------------------------------------------
extern "C" void kernel_launch(void* const* d_in, const int* in_sizes, int n_in,
                              void* d_out, int out_size)
{
    const float* X   = (const float*)d_in[0];   // inputs  [N, D]
    const float* CB  = (const float*)d_in[1];   // codebook [K, D]
    const float* ECS = (const float*)d_in[2];   // ema_cluster_size [K]
    const float* EW  = (const float*)d_in[3];   // ema_w [K, D]
    float* out = (float*)d_out;

    const size_t OQ = 0;
    const size_t OL = (size_t)N_TOK * D;        // vq_loss
    const size_t OI = OL + 1;                   // indices
    const size_t OP = OI + N_TOK;               // perplexity
    const size_t OC = OP + 1;                   // new_cs
    const size_t OE = OC + K;                   // new_ema_w
    const size_t OW = OE + (size_t)K * D;       // new_weight

    vq_prep<<<(K * D + 255) / 256, 256>>>();
    vq_cs<<<K / 8, 256>>>(CB);
    vq_main<<<N_TOK / BM, 256>>>(X, CB, out + OQ, out + OI);
    vq_finalize<<<1, K>>>(ECS, out + OC, out + OP, out + OL);
    vq_ema<<<(K * D) / 256, 256>>>(EW, out + OC, out + OE, out + OW);
}

// round 6
// speedup vs baseline: 1.0882x; 1.0022x over previous
#include <cuda_runtime.h>
#include <stdint.h>

// Problem constants
#define N_TOK 65536
#define D     256
#define K     1024

// GEMM tiling
#define BM 128
#define BN 128
#define BK 16
#define TM 8
#define TN 8

// Packed fp32x2 FMA (SASS FFMA2, sm_103a). Exact per-lane fp32 FMA.
#define FMA_F32X2(d, a, b, c) \
    asm("fma.rn.f32x2 %0, %1, %2, %3;" : "=l"(d) : "l"(a), "l"(b), "l"(c))
#define PACK_DUP_F32X2(out, f) \
    asm("mov.b64 %0, {%1, %1};" : "=l"(out) : "r"(__float_as_uint(f)))
#define UNPACK_F32X2(lo, hi, in) \
    asm("mov.b64 {%0, %1}, %2;" : "=f"(lo), "=f"(hi) : "l"(in))

// Scratch (no cudaMalloc allowed)
__device__ float g_counts[K];
__device__ float g_dw[K * D];
__device__ float g_cs[K];
__device__ unsigned long long g_loss;

// ---------------------------------------------------------------------------
// Zero scratch
// ---------------------------------------------------------------------------
__global__ void vq_prep() {
    int i = blockIdx.x * blockDim.x + threadIdx.x;
    if (i < K * D) g_dw[i] = 0.0f;
    if (i < K)     g_counts[i] = 0.0f;
    if (i == 0)    g_loss = 0ull;
}

// ---------------------------------------------------------------------------
// Codebook squared norms: g_cs[k] = sum_d CB[k,d]^2   (one warp per row)
// ---------------------------------------------------------------------------
__global__ void vq_cs(const float* __restrict__ CB) {
    int w = (blockIdx.x * blockDim.x + threadIdx.x) >> 5;
    int lane = threadIdx.x & 31;
    if (w >= K) return;
    const float* row = CB + (size_t)w * D + lane * 8;
    float4 v0 = *(const float4*)row;
    float4 v1 = *(const float4*)(row + 4);
    float s = v0.x * v0.x + v0.y * v0.y + v0.z * v0.z + v0.w * v0.w
            + v1.x * v1.x + v1.y * v1.y + v1.z * v1.z + v1.w * v1.w;
    #pragma unroll
    for (int o = 16; o > 0; o >>= 1) s += __shfl_xor_sync(0xffffffffu, s, o);
    if (lane == 0) g_cs[w] = s;
}

// ---------------------------------------------------------------------------
// Main fused kernel: distance GEMM (FFMA2) + argmin + gather + scatter + loss
// One block handles BM=128 tokens against all K=1024 codes.
// ---------------------------------------------------------------------------
__global__ __launch_bounds__(256, 2) void vq_main(
    const float* __restrict__ X, const float* __restrict__ CB,
    float* __restrict__ outQ, float* __restrict__ outIdx)
{
    __shared__ __align__(16) float As[BK][BM];
    __shared__ __align__(16) float Bs[BK][BN];
    __shared__ float rxs[BM];
    __shared__ float red_d[16][BM];
    __shared__ int   red_i[16][BM];
    __shared__ int   bestI[BM];
    __shared__ float bestD[BM];

    const int tid = threadIdx.x;
    const int tx = tid & 15;   // code-column group
    const int ty = tid >> 4;   // token-row group
    const int tok0 = blockIdx.x * BM;

    // Per-token ||x||^2 (constant offset; reproduces reference fp32 grid)
    if (tid < BM) {
        const float* xr = X + (size_t)(tok0 + tid) * D;
        float s = 0.0f;
        #pragma unroll 8
        for (int j = 0; j < D; j += 4) {
            float4 v = *(const float4*)(xr + j);
            s += v.x * v.x; s += v.y * v.y; s += v.z * v.z; s += v.w * v.w;
        }
        rxs[tid] = s;
    }

    float bd[TM];
    int   bi[TM];
    #pragma unroll
    for (int r = 0; r < TM; r++) { bd[r] = 3.4e38f; bi[r] = 0; }

    __syncthreads();

    for (int kc = 0; kc < K / BN; kc++) {
        // acc2[r][c2] packs columns (2*c2, 2*c2+1) of the 8x8 micro-tile
        unsigned long long acc2[TM][TN / 2];
        #pragma unroll
        for (int r = 0; r < TM; r++)
            #pragma unroll
            for (int c = 0; c < TN / 2; c++) acc2[r][c] = 0ull;

        for (int dd = 0; dd < D; dd += BK) {
            // Stage A (tokens) and B (codes) tiles, transposed into [k][row]
            #pragma unroll
            for (int i = 0; i < 2; i++) {
                int li = tid + i * 256;           // 0..511
                int r  = li >> 2;                 // 0..127
                int cg = (li & 3) << 2;           // 0,4,8,12
                float4 va = *(const float4*)(X  + (size_t)(tok0 + r) * D + dd + cg);
                As[cg + 0][r] = va.x; As[cg + 1][r] = va.y;
                As[cg + 2][r] = va.z; As[cg + 3][r] = va.w;
                float4 vb = *(const float4*)(CB + (size_t)(kc * BN + r) * D + dd + cg);
                Bs[cg + 0][r] = vb.x; Bs[cg + 1][r] = vb.y;
                Bs[cg + 2][r] = vb.z; Bs[cg + 3][r] = vb.w;
            }
            __syncthreads();

            #pragma unroll
            for (int k = 0; k < BK; k++) {
                float a_[TM];
                *(float4*)(a_)     = *(const float4*)&As[k][ty * TM];
                *(float4*)(a_ + 4) = *(const float4*)&As[k][ty * TM + 4];
                // b pairs come directly as u64 views of the float4 loads
                ulonglong2 b01 = *(const ulonglong2*)&Bs[k][tx * TN];
                ulonglong2 b23 = *(const ulonglong2*)&Bs[k][tx * TN + 4];
                #pragma unroll
                for (int r = 0; r < TM; r++) {
                    unsigned long long pa;
                    PACK_DUP_F32X2(pa, a_[r]);
                    FMA_F32X2(acc2[r][0], pa, b01.x, acc2[r][0]);
                    FMA_F32X2(acc2[r][1], pa, b01.y, acc2[r][1]);
                    FMA_F32X2(acc2[r][2], pa, b23.x, acc2[r][2]);
                    FMA_F32X2(acc2[r][3], pa, b23.y, acc2[r][3]);
                }
            }
            __syncthreads();
        }

        // Chunk epilogue: d = (rx + cs) - 2*dot ; running argmin (strict <,
        // k ascending -> first-index tie-break within this thread)
        #pragma unroll
        for (int c2 = 0; c2 < TN / 2; c2++) {
            int kidx = kc * BN + tx * TN + 2 * c2;
            float cs0 = g_cs[kidx];
            float cs1 = g_cs[kidx + 1];
            #pragma unroll
            for (int r = 0; r < TM; r++) {
                float lo, hi;
                UNPACK_F32X2(lo, hi, acc2[r][c2]);
                float rx = rxs[ty * TM + r];
                float d0 = (rx + cs0) - 2.0f * lo;
                float d1 = (rx + cs1) - 2.0f * hi;
                if (d0 < bd[r]) { bd[r] = d0; bi[r] = kidx; }
                if (d1 < bd[r]) { bd[r] = d1; bi[r] = kidx + 1; }
            }
        }
    }

    // Cross-thread argmin reduce (16 tx threads share each token row)
    #pragma unroll
    for (int r = 0; r < TM; r++) {
        red_d[tx][ty * TM + r] = bd[r];
        red_i[tx][ty * TM + r] = bi[r];
    }
    __syncthreads();

    if (tid < BM) {
        float best = 3.4e38f;
        int bidx = K;
        #pragma unroll
        for (int t = 0; t < 16; t++) {
            float d = red_d[t][tid];
            int   ii = red_i[t][tid];
            if (d < best || (d == best && ii < bidx)) { best = d; bidx = ii; }
        }
        bestI[tid] = bidx;
        bestD[tid] = best;
        outIdx[tok0 + tid] = (float)bidx;
        atomicAdd(&g_counts[bidx], 1.0f);   // exact: integer-valued fp32 sums
    }
    __syncthreads();

    // Deterministic loss accumulation: scaled int64
    if (tid == 0) {
        double s = 0.0;
        for (int r = 0; r < BM; r++) s += (double)bestD[r];
        atomicAdd(&g_loss, (unsigned long long)llrint(s * 1048576.0));
    }

    // Gather quantized rows + scatter dw
    for (int i = tid; i < BM * (D / 4); i += 256) {
        int row = i >> 6;
        int c4  = (i & 63) << 2;
        int b   = bestI[row];
        float4 q = *(const float4*)(CB + (size_t)b * D + c4);
        *(float4*)(outQ + (size_t)(tok0 + row) * D + c4) = q;
        float4 xv = *(const float4*)(X + (size_t)(tok0 + row) * D + c4);
        float* dwp = g_dw + (size_t)b * D + c4;
        atomicAdd(dwp + 0, xv.x);
        atomicAdd(dwp + 1, xv.y);
        atomicAdd(dwp + 2, xv.z);
        atomicAdd(dwp + 3, xv.w);
    }
}

// ---------------------------------------------------------------------------
// Finalize: new_cs (Laplace-smoothed), perplexity, vq_loss. One block, K thr.
// ---------------------------------------------------------------------------
__global__ void vq_finalize(const float* __restrict__ ecs,
                            float* __restrict__ out_cs,
                            float* __restrict__ out_perp,
                            float* __restrict__ out_loss)
{
    __shared__ float sbuf[K];
    int k = threadIdx.x;
    float cnt = g_counts[k];
    float cn = 0.99f * ecs[k] + 0.01f * cnt;

    sbuf[k] = cn;
    __syncthreads();
    for (int s = K / 2; s > 0; s >>= 1) {
        if (k < s) sbuf[k] += sbuf[k + s];
        __syncthreads();
    }
    float ntot = sbuf[0];
    __syncthreads();

    out_cs[k] = (cn + 1e-5f) / (ntot + 0.01024f) * ntot;

    float p = cnt * (1.0f / 65536.0f);
    sbuf[k] = p * logf(p + 1e-10f);
    __syncthreads();
    for (int s = K / 2; s > 0; s >>= 1) {
        if (k < s) sbuf[k] += sbuf[k + s];
        __syncthreads();
    }
    if (k == 0) {
        out_perp[0] = expf(-sbuf[0]);
        double loss = (double)g_loss * (1.0 / 1048576.0) / (65536.0 * 256.0);
        out_loss[0] = 0.25f * (float)loss;
    }
}

// ---------------------------------------------------------------------------
// EMA codebook update + normalized weight
// ---------------------------------------------------------------------------
__global__ void vq_ema(const float* __restrict__ emaw,
                       const float* __restrict__ ncs,
                       float* __restrict__ outE,
                       float* __restrict__ outW)
{
    int i = blockIdx.x * blockDim.x + threadIdx.x;   // < K*D
    float w = 0.99f * emaw[i] + 0.01f * g_dw[i];
    outE[i] = w;
    outW[i] = w / ncs[i >> 8];
}

// ---------------------------------------------------------------------------
// Launch: outputs concatenated in reference return order, all float32:
//   quantized_st [N*D] | vq_loss [1] | indices [N] | perplexity [1]
//   | new_cs [K] | new_ema_w [K*D] | new_weight [K*D]
// ---------------------------------------------------------------------------
extern "C" void kernel_launch(void* const* d_in, const int* in_sizes, int n_in,
                              void* d_out, int out_size)
{
    const float* X   = (const float*)d_in[0];   // inputs  [N, D]
    const float* CB  = (const float*)d_in[1];   // codebook [K, D]
    const float* ECS = (const float*)d_in[2];   // ema_cluster_size [K]
    const float* EW  = (const float*)d_in[3];   // ema_w [K, D]
    float* out = (float*)d_out;

    const size_t OQ = 0;
    const size_t OL = (size_t)N_TOK * D;        // vq_loss
    const size_t OI = OL + 1;                   // indices
    const size_t OP = OI + N_TOK;               // perplexity
    const size_t OC = OP + 1;                   // new_cs
    const size_t OE = OC + K;                   // new_ema_w
    const size_t OW = OE + (size_t)K * D;       // new_weight

    vq_prep<<<(K * D + 255) / 256, 256>>>();
    vq_cs<<<K / 8, 256>>>(CB);
    vq_main<<<N_TOK / BM, 256>>>(X, CB, out + OQ, out + OI);
    vq_finalize<<<1, K>>>(ECS, out + OC, out + OP, out + OL);
    vq_ema<<<(K * D) / 256, 256>>>(EW, out + OC, out + OE, out + OW);
}